// round 1
// baseline (speedup 1.0000x reference)
#include <cuda_runtime.h>
#include <math.h>

#define N_NODES 200000
#define WDIM    512
#define HDIM    1024
#define NGRAPH  2000

// -------- scratch (__device__ globals: no allocation allowed) --------
__device__ float g_xraw[(size_t)N_NODES * WDIM];    // pre-GEMM output (pre-LN)
__device__ float g_xx  [(size_t)N_NODES * WDIM];    // post-LN nodes
__device__ float g_t   [(size_t)N_NODES * HDIM];    // mem+msg fused branch
__device__ float g_pooled[NGRAPH * WDIM];
__device__ float g_msg   [NGRAPH * HDIM];

// ---------------------------------------------------------------
// zero pooled accumulator (must re-zero every launch: graph replay)
// ---------------------------------------------------------------
__global__ void zero_pooled_kernel() {
    int i = blockIdx.x * blockDim.x + threadIdx.x;
    if (i < NGRAPH * WDIM) g_pooled[i] = 0.0f;
}

// ---------------------------------------------------------------
// GEMM: C[M,N] = A[M,K] @ B[K,N]  (+ fused epilogues)
// 128x128 block tile, BK=8, 256 threads, 8x8 per thread (4+4 split),
// double-buffered smem.
// MODE 0: C = acc + bias                               (pre)
// MODE 1: C = gelu(acc + bias)                         (msg)
// MODE 2: C = gelu(acc + bias) + scale*msg[batch[m]]   (mem)
// MODE 3: y = acc + bias; C[m]=x[m]+y; out2[m]=y       (post)
// ---------------------------------------------------------------
#define BM 128
#define BN 128
#define BK 8
#define ASTRIDE 132   // pad to kill store-bank conflicts

__device__ __forceinline__ float gelu_exact(float v) {
    return 0.5f * v * (1.0f + erff(v * 0.70710678118654752f));
}

template<int MODE>
__global__ __launch_bounds__(256, 2)
void gemm_fused(const float* __restrict__ A, const float* __restrict__ B,
                float* __restrict__ C, int M, int N, int K,
                const float* __restrict__ bias,
                const float* __restrict__ extra,   // MODE2: g_msg, MODE3: x
                const int*   __restrict__ batch,
                const float* __restrict__ zero,
                float* __restrict__ out2)
{
    __shared__ float As[2][BK][ASTRIDE];
    __shared__ float Bs[2][BK][BN];

    const int tid = threadIdx.x;
    const int bm = blockIdx.y * BM;
    const int bn = blockIdx.x * BN;

    const int a_row = tid >> 1;            // 0..127
    const int a_col = (tid & 1) << 2;      // 0 or 4
    const int b_row = tid >> 5;            // 0..7
    const int b_col = (tid & 31) << 2;     // 0..124

    const int tx = tid & 15;
    const int ty = tid >> 4;

    float c[8][8];
    #pragma unroll
    for (int i = 0; i < 8; i++)
        #pragma unroll
        for (int j = 0; j < 8; j++) c[i][j] = 0.0f;

    float4 a_reg, b_reg;
    const int KT = K / BK;

    // prefetch tile 0
    {
        int gm = bm + a_row;
        if (gm < M) a_reg = *(const float4*)(A + (size_t)gm * K + a_col);
        else        a_reg = make_float4(0.f, 0.f, 0.f, 0.f);
        b_reg = *(const float4*)(B + (size_t)b_row * N + bn + b_col);
        As[0][a_col + 0][a_row] = a_reg.x;
        As[0][a_col + 1][a_row] = a_reg.y;
        As[0][a_col + 2][a_row] = a_reg.z;
        As[0][a_col + 3][a_row] = a_reg.w;
        *(float4*)&Bs[0][b_row][b_col] = b_reg;
    }
    __syncthreads();

    for (int kt = 0; kt < KT; kt++) {
        const int cur = kt & 1, nxt = cur ^ 1;
        if (kt + 1 < KT) {
            const int k0 = (kt + 1) * BK;
            int gm = bm + a_row;
            if (gm < M) a_reg = *(const float4*)(A + (size_t)gm * K + k0 + a_col);
            else        a_reg = make_float4(0.f, 0.f, 0.f, 0.f);
            b_reg = *(const float4*)(B + (size_t)(k0 + b_row) * N + bn + b_col);
        }
        #pragma unroll
        for (int k = 0; k < BK; k++) {
            float af[8], bf[8];
            *(float4*)&af[0] = *(const float4*)&As[cur][k][ty * 4];
            *(float4*)&af[4] = *(const float4*)&As[cur][k][64 + ty * 4];
            *(float4*)&bf[0] = *(const float4*)&Bs[cur][k][tx * 4];
            *(float4*)&bf[4] = *(const float4*)&Bs[cur][k][64 + tx * 4];
            #pragma unroll
            for (int i = 0; i < 8; i++)
                #pragma unroll
                for (int j = 0; j < 8; j++)
                    c[i][j] += af[i] * bf[j];
        }
        if (kt + 1 < KT) {
            As[nxt][a_col + 0][a_row] = a_reg.x;
            As[nxt][a_col + 1][a_row] = a_reg.y;
            As[nxt][a_col + 2][a_row] = a_reg.z;
            As[nxt][a_col + 3][a_row] = a_reg.w;
            *(float4*)&Bs[nxt][b_row][b_col] = b_reg;
        }
        __syncthreads();
    }

    // ---------------- epilogue ----------------
    float scale = 1.0f;
    if (MODE == 2) scale = expf(zero[0]);

    #pragma unroll
    for (int i = 0; i < 8; i++) {
        const int roff = (i < 4) ? (ty * 4 + i) : (64 + ty * 4 + (i - 4));
        const int row = bm + roff;
        if (row >= M) continue;
        int g = 0;
        if (MODE == 2) g = batch[row];
        #pragma unroll
        for (int jj = 0; jj < 2; jj++) {
            const int coff = (jj == 0) ? (tx * 4) : (64 + tx * 4);
            const int col = bn + coff;
            float4 bsv = *(const float4*)(bias + col);
            float v[4];
            v[0] = c[i][jj * 4 + 0] + bsv.x;
            v[1] = c[i][jj * 4 + 1] + bsv.y;
            v[2] = c[i][jj * 4 + 2] + bsv.z;
            v[3] = c[i][jj * 4 + 3] + bsv.w;

            if (MODE == 1 || MODE == 2) {
                #pragma unroll
                for (int q = 0; q < 4; q++) v[q] = gelu_exact(v[q]);
            }
            if (MODE == 2) {
                float4 mv = *(const float4*)(extra + (size_t)g * HDIM + col);
                v[0] += scale * mv.x; v[1] += scale * mv.y;
                v[2] += scale * mv.z; v[3] += scale * mv.w;
            }
            if (MODE == 3) {
                float4 xv = *(const float4*)(extra + (size_t)row * N + col);
                float4 yo = make_float4(v[0], v[1], v[2], v[3]);
                *(float4*)(out2 + (size_t)row * N + col) = yo;
                float4 o1 = make_float4(xv.x + v[0], xv.y + v[1],
                                        xv.z + v[2], xv.w + v[3]);
                *(float4*)(C + (size_t)row * N + col) = o1;
            } else {
                float4 o = make_float4(v[0], v[1], v[2], v[3]);
                *(float4*)(C + (size_t)row * N + col) = o;
            }
        }
    }
}

// ---------------------------------------------------------------
// LayerNorm + segment pooling. Block = 128 threads, 32 consecutive
// rows per block. batch is sorted -> accumulate per-segment partial
// in registers, atomicAdd only on segment change (~1.3 flushes/blk).
// ---------------------------------------------------------------
#define LN_ROWS 32
__global__ __launch_bounds__(128)
void ln_pool_kernel(const float* __restrict__ xraw, float* __restrict__ xx,
                    float* __restrict__ pooled, const int* __restrict__ batch)
{
    __shared__ float shs[4], shs2[4];
    const int tid  = threadIdx.x;
    const int lane = tid & 31, warp = tid >> 5;
    const int row0 = blockIdx.x * LN_ROWS;

    float acc0 = 0.f, acc1 = 0.f, acc2 = 0.f, acc3 = 0.f;
    int cur_g = batch[row0];

    for (int r = 0; r < LN_ROWS; r++) {
        const int row = row0 + r;
        float4 v = *(const float4*)(xraw + (size_t)row * WDIM + tid * 4);
        float s  = v.x + v.y + v.z + v.w;
        float s2 = v.x * v.x + v.y * v.y + v.z * v.z + v.w * v.w;
        #pragma unroll
        for (int o = 16; o > 0; o >>= 1) {
            s  += __shfl_xor_sync(0xffffffffu, s,  o);
            s2 += __shfl_xor_sync(0xffffffffu, s2, o);
        }
        if (lane == 0) { shs[warp] = s; shs2[warp] = s2; }
        __syncthreads();
        float sum  = shs[0] + shs[1] + shs[2] + shs[3];
        float sum2 = shs2[0] + shs2[1] + shs2[2] + shs2[3];
        __syncthreads();

        const float mu  = sum * (1.0f / WDIM);
        const float var = sum2 * (1.0f / WDIM) - mu * mu;
        const float rs  = rsqrtf(var + 1e-5f);
        v.x = (v.x - mu) * rs; v.y = (v.y - mu) * rs;
        v.z = (v.z - mu) * rs; v.w = (v.w - mu) * rs;
        *(float4*)(xx + (size_t)row * WDIM + tid * 4) = v;

        const int g = batch[row];
        if (g != cur_g) {
            float* p = pooled + (size_t)cur_g * WDIM + tid * 4;
            atomicAdd(p + 0, acc0); atomicAdd(p + 1, acc1);
            atomicAdd(p + 2, acc2); atomicAdd(p + 3, acc3);
            acc0 = acc1 = acc2 = acc3 = 0.f;
            cur_g = g;
        }
        acc0 += v.x; acc1 += v.y; acc2 += v.z; acc3 += v.w;
    }
    float* p = pooled + (size_t)cur_g * WDIM + tid * 4;
    atomicAdd(p + 0, acc0); atomicAdd(p + 1, acc1);
    atomicAdd(p + 2, acc2); atomicAdd(p + 3, acc3);
}

// ---------------------------------------------------------------
extern "C" void kernel_launch(void* const* d_in, const int* in_sizes, int n_in,
                              void* d_out, int out_size)
{
    const float* x      = (const float*)d_in[0];
    const int*   batch  = (const int*)  d_in[1];
    const float* pre_w  = (const float*)d_in[2];
    const float* pre_b  = (const float*)d_in[3];
    const float* mem_w  = (const float*)d_in[4];
    const float* mem_b  = (const float*)d_in[5];
    const float* msg_w  = (const float*)d_in[6];
    const float* msg_b  = (const float*)d_in[7];
    const float* post_w = (const float*)d_in[8];
    const float* post_b = (const float*)d_in[9];
    const float* zero   = (const float*)d_in[10];

    float* out1 = (float*)d_out;
    float* out2 = out1 + (size_t)N_NODES * WDIM;

    float *xraw, *xx, *t, *pooled, *msg;
    cudaGetSymbolAddress((void**)&xraw,   g_xraw);
    cudaGetSymbolAddress((void**)&xx,     g_xx);
    cudaGetSymbolAddress((void**)&t,      g_t);
    cudaGetSymbolAddress((void**)&pooled, g_pooled);
    cudaGetSymbolAddress((void**)&msg,    g_msg);

    const dim3 blk(256);
    const int gy = (N_NODES + BM - 1) / BM;           // 1563

    // 1. zero pooled accumulator
    zero_pooled_kernel<<<(NGRAPH * WDIM + 255) / 256, 256>>>();

    // 2. pre GEMM: xraw = x @ pre_w + pre_b
    gemm_fused<0><<<dim3(WDIM / BN, gy), blk>>>(
        x, pre_w, xraw, N_NODES, WDIM, WDIM, pre_b,
        nullptr, nullptr, nullptr, nullptr);

    // 3. LayerNorm + segment pooling
    ln_pool_kernel<<<N_NODES / LN_ROWS, 128>>>(xraw, xx, pooled, batch);

    // 4. msg GEMM: msg = gelu(pooled @ msg_w + msg_b)
    gemm_fused<1><<<dim3(HDIM / BN, (NGRAPH + BM - 1) / BM), blk>>>(
        pooled, msg_w, msg, NGRAPH, HDIM, WDIM, msg_b,
        nullptr, nullptr, nullptr, nullptr);

    // 5. mem GEMM fused: t = gelu(xx @ mem_w + mem_b) + exp(zero)*msg[batch]
    gemm_fused<2><<<dim3(HDIM / BN, gy), blk>>>(
        xx, mem_w, t, N_NODES, HDIM, WDIM, mem_b,
        msg, batch, zero, nullptr);

    // 6. post GEMM fused: y = t @ post_w + post_b; out1 = x + y; out2 = y
    gemm_fused<3><<<dim3(WDIM / BN, gy), blk>>>(
        t, post_w, out1, N_NODES, WDIM, HDIM, post_b,
        x, nullptr, nullptr, out2);
}

// round 5
// speedup vs baseline: 1.8472x; 1.8472x over previous
#include <cuda_runtime.h>
#include <cuda_bf16.h>
#include <stdint.h>
#include <math.h>

#define N_NODES 200000
#define WDIM    512
#define HDIM    1024
#define NGRAPH  2000

// -------- scratch (__device__ globals: no allocation allowed) --------
__device__ float g_xraw[(size_t)N_NODES * WDIM];
__device__ float g_xx  [(size_t)N_NODES * WDIM];
__device__ float g_t   [(size_t)N_NODES * HDIM];
__device__ float g_pooled[NGRAPH * WDIM];
__device__ float g_msg   [NGRAPH * HDIM];

__global__ void zero_pooled_kernel() {
    int i = blockIdx.x * blockDim.x + threadIdx.x;
    if (i < NGRAPH * WDIM) g_pooled[i] = 0.0f;
}

// ---------------------------------------------------------------
// bf16 split-precision tensor-core GEMM (3-product scheme)
// C = A@B with A,B fp32; computed as Ahi*Bhi + Ahi*Blo + Alo*Bhi
// 128x128x32 tile, 256 threads (8 warps, 2x4), warp = 64x32,
// mma.sync.m16n8k16.bf16 with fp32 accumulators.
// MODE 0: C = acc + bias                               (pre)
// MODE 1: C = gelu(acc + bias)                         (msg)
// MODE 2: C = gelu(acc + bias) + scale*msg[batch[m]]   (mem)
// MODE 3: y = acc + bias; C[m]=x[m]+y; out2[m]=y       (post)
// ---------------------------------------------------------------
#define BM 128
#define BN 128
#define BKF 32
#define ASTR 56    // bf16 elems; 112B row stride (16B multiple, 8-row period)
#define BSTR 136   // 272B row stride

__device__ __forceinline__ float gelu_exact(float v) {
    return 0.5f * v * (1.0f + erff(v * 0.70710678118654752f));
}
__device__ __forceinline__ unsigned int s2u(const void* p) {
    return (unsigned int)__cvta_generic_to_shared(p);
}

#define LDSM4(R, ADDR) asm volatile( \
    "ldmatrix.sync.aligned.m8n8.x4.shared.b16 {%0,%1,%2,%3}, [%4];" \
    : "=r"((R)[0]), "=r"((R)[1]), "=r"((R)[2]), "=r"((R)[3]) : "r"(ADDR))

#define LDSM2T(R, ADDR) asm volatile( \
    "ldmatrix.sync.aligned.m8n8.x2.trans.shared.b16 {%0,%1}, [%2];" \
    : "=r"((R)[0]), "=r"((R)[1]) : "r"(ADDR))

#define MMA_BF16(D, Ar, Br) asm volatile( \
    "mma.sync.aligned.m16n8k16.row.col.f32.bf16.bf16.f32 " \
    "{%0,%1,%2,%3},{%4,%5,%6,%7},{%8,%9},{%0,%1,%2,%3};" \
    : "+f"((D)[0]), "+f"((D)[1]), "+f"((D)[2]), "+f"((D)[3]) \
    : "r"((Ar)[0]), "r"((Ar)[1]), "r"((Ar)[2]), "r"((Ar)[3]), \
      "r"((Br)[0]), "r"((Br)[1]))

template<int MODE>
__global__ __launch_bounds__(256)
void gemm_bf16x3(const float* __restrict__ A, const float* __restrict__ B,
                 float* __restrict__ C, int M, int N, int K,
                 const float* __restrict__ bias,
                 const float* __restrict__ extra,   // MODE2: g_msg, MODE3: x
                 const int*   __restrict__ batch,
                 const float* __restrict__ zero,
                 float* __restrict__ out2)
{
    __shared__ __nv_bfloat16 Ah[BM * ASTR];
    __shared__ __nv_bfloat16 Al[BM * ASTR];
    __shared__ __nv_bfloat16 Bh[BKF * BSTR];
    __shared__ __nv_bfloat16 Bl[BKF * BSTR];

    const int tid  = threadIdx.x;
    const int lane = tid & 31, warp = tid >> 5;
    const int warp_m = warp >> 2;      // 0..1
    const int warp_n = warp & 3;       // 0..3
    const int bm = blockIdx.y * BM;
    const int bn = blockIdx.x * BN;

    float acc[4][4][4];
    #pragma unroll
    for (int a = 0; a < 4; a++)
        #pragma unroll
        for (int b = 0; b < 4; b++)
            #pragma unroll
            for (int c = 0; c < 4; c++) acc[a][b][c] = 0.0f;

    float4 areg[4], breg[4];
    const int KT = K / BKF;

    auto load_regs = [&](int k0) {
        #pragma unroll
        for (int i = 0; i < 4; i++) {
            int f = tid + 256 * i;
            int arow = f >> 3, ac4 = f & 7;
            int gm = bm + arow;
            if (gm < M) areg[i] = *(const float4*)(A + (size_t)gm * K + k0 + ac4 * 4);
            else        areg[i] = make_float4(0.f, 0.f, 0.f, 0.f);
            int brow = f >> 5, bc4 = f & 31;
            breg[i] = *(const float4*)(B + (size_t)(k0 + brow) * N + bn + bc4 * 4);
        }
    };

    auto store_smem = [&]() {
        #pragma unroll
        for (int i = 0; i < 4; i++) {
            int f = tid + 256 * i;
            {   // A: split into hi/lo
                int arow = f >> 3, ac4 = f & 7;
                float vs[4] = { areg[i].x, areg[i].y, areg[i].z, areg[i].w };
                __nv_bfloat16 h[4], l[4];
                #pragma unroll
                for (int q = 0; q < 4; q++) {
                    h[q] = __float2bfloat16(vs[q]);
                    l[q] = __float2bfloat16(vs[q] - __bfloat162float(h[q]));
                }
                __nv_bfloat16* pa = &Ah[arow * ASTR + ac4 * 4];
                __nv_bfloat16* pl = &Al[arow * ASTR + ac4 * 4];
                *(__nv_bfloat162*)(pa + 0) = __halves2bfloat162(h[0], h[1]);
                *(__nv_bfloat162*)(pa + 2) = __halves2bfloat162(h[2], h[3]);
                *(__nv_bfloat162*)(pl + 0) = __halves2bfloat162(l[0], l[1]);
                *(__nv_bfloat162*)(pl + 2) = __halves2bfloat162(l[2], l[3]);
            }
            {   // B
                int brow = f >> 5, bc4 = f & 31;
                float vs[4] = { breg[i].x, breg[i].y, breg[i].z, breg[i].w };
                __nv_bfloat16 h[4], l[4];
                #pragma unroll
                for (int q = 0; q < 4; q++) {
                    h[q] = __float2bfloat16(vs[q]);
                    l[q] = __float2bfloat16(vs[q] - __bfloat162float(h[q]));
                }
                __nv_bfloat16* pb = &Bh[brow * BSTR + bc4 * 4];
                __nv_bfloat16* pl = &Bl[brow * BSTR + bc4 * 4];
                *(__nv_bfloat162*)(pb + 0) = __halves2bfloat162(h[0], h[1]);
                *(__nv_bfloat162*)(pb + 2) = __halves2bfloat162(h[2], h[3]);
                *(__nv_bfloat162*)(pl + 0) = __halves2bfloat162(l[0], l[1]);
                *(__nv_bfloat162*)(pl + 2) = __halves2bfloat162(l[2], l[3]);
            }
        }
    };

    auto compute = [&]() {
        #pragma unroll
        for (int kk = 0; kk < 2; kk++) {
            unsigned int ah[4][4], al[4][4], bh[4][2], bl[4][2];
            #pragma unroll
            for (int mt = 0; mt < 4; mt++) {
                int row = warp_m * 64 + mt * 16 + (lane & 15);
                int col = kk * 16 + (lane >> 4) * 8;
                LDSM4(ah[mt], s2u(&Ah[row * ASTR + col]));
                LDSM4(al[mt], s2u(&Al[row * ASTR + col]));
            }
            #pragma unroll
            for (int nt = 0; nt < 4; nt++) {
                int row = kk * 16 + (lane & 15);
                int col = warp_n * 32 + nt * 8;
                LDSM2T(bh[nt], s2u(&Bh[row * BSTR + col]));
                LDSM2T(bl[nt], s2u(&Bl[row * BSTR + col]));
            }
            #pragma unroll
            for (int mt = 0; mt < 4; mt++)
                #pragma unroll
                for (int nt = 0; nt < 4; nt++) {
                    MMA_BF16(acc[mt][nt], ah[mt], bh[nt]);
                    MMA_BF16(acc[mt][nt], ah[mt], bl[nt]);
                    MMA_BF16(acc[mt][nt], al[mt], bh[nt]);
                }
        }
    };

    load_regs(0);
    store_smem();
    __syncthreads();
    for (int kt = 0; kt < KT; kt++) {
        if (kt + 1 < KT) load_regs((kt + 1) * BKF);
        compute();
        if (kt + 1 < KT) {
            __syncthreads();
            store_smem();
            __syncthreads();
        }
    }

    // ---------------- epilogue ----------------
    float scale = 1.0f;
    if (MODE == 2) scale = expf(zero[0]);

    #pragma unroll
    for (int mt = 0; mt < 4; mt++) {
        const int rbase = bm + warp_m * 64 + mt * 16 + (lane >> 2);
        #pragma unroll
        for (int half = 0; half < 2; half++) {
            const int row = rbase + half * 8;
            if (row >= M) continue;
            int g = 0;
            if (MODE == 2) g = batch[row];
            #pragma unroll
            for (int nt = 0; nt < 4; nt++) {
                const int col = bn + warp_n * 32 + nt * 8 + (lane & 3) * 2;
                float v0 = acc[mt][nt][half * 2 + 0] + bias[col];
                float v1 = acc[mt][nt][half * 2 + 1] + bias[col + 1];
                if (MODE == 1 || MODE == 2) {
                    v0 = gelu_exact(v0);
                    v1 = gelu_exact(v1);
                }
                if (MODE == 2) {
                    float2 mv = *(const float2*)(extra + (size_t)g * N + col);
                    v0 += scale * mv.x;
                    v1 += scale * mv.y;
                }
                if (MODE == 3) {
                    float2 xv = *(const float2*)(extra + (size_t)row * N + col);
                    *(float2*)(out2 + (size_t)row * N + col) = make_float2(v0, v1);
                    *(float2*)(C + (size_t)row * N + col) =
                        make_float2(xv.x + v0, xv.y + v1);
                } else {
                    *(float2*)(C + (size_t)row * N + col) = make_float2(v0, v1);
                }
            }
        }
    }
}

// ---------------------------------------------------------------
// LayerNorm + segment pooling (unchanged from R1)
// ---------------------------------------------------------------
#define LN_ROWS 32
__global__ __launch_bounds__(128)
void ln_pool_kernel(const float* __restrict__ xraw, float* __restrict__ xx,
                    float* __restrict__ pooled, const int* __restrict__ batch)
{
    __shared__ float shs[4], shs2[4];
    const int tid  = threadIdx.x;
    const int lane = tid & 31, warp = tid >> 5;
    const int row0 = blockIdx.x * LN_ROWS;

    float acc0 = 0.f, acc1 = 0.f, acc2 = 0.f, acc3 = 0.f;
    int cur_g = batch[row0];

    for (int r = 0; r < LN_ROWS; r++) {
        const int row = row0 + r;
        float4 v = *(const float4*)(xraw + (size_t)row * WDIM + tid * 4);
        float s  = v.x + v.y + v.z + v.w;
        float s2 = v.x * v.x + v.y * v.y + v.z * v.z + v.w * v.w;
        #pragma unroll
        for (int o = 16; o > 0; o >>= 1) {
            s  += __shfl_xor_sync(0xffffffffu, s,  o);
            s2 += __shfl_xor_sync(0xffffffffu, s2, o);
        }
        if (lane == 0) { shs[warp] = s; shs2[warp] = s2; }
        __syncthreads();
        float sum  = shs[0] + shs[1] + shs[2] + shs[3];
        float sum2 = shs2[0] + shs2[1] + shs2[2] + shs2[3];
        __syncthreads();

        const float mu  = sum * (1.0f / WDIM);
        const float var = sum2 * (1.0f / WDIM) - mu * mu;
        const float rs  = rsqrtf(var + 1e-5f);
        v.x = (v.x - mu) * rs; v.y = (v.y - mu) * rs;
        v.z = (v.z - mu) * rs; v.w = (v.w - mu) * rs;
        *(float4*)(xx + (size_t)row * WDIM + tid * 4) = v;

        const int g = batch[row];
        if (g != cur_g) {
            float* p = pooled + (size_t)cur_g * WDIM + tid * 4;
            atomicAdd(p + 0, acc0); atomicAdd(p + 1, acc1);
            atomicAdd(p + 2, acc2); atomicAdd(p + 3, acc3);
            acc0 = acc1 = acc2 = acc3 = 0.f;
            cur_g = g;
        }
        acc0 += v.x; acc1 += v.y; acc2 += v.z; acc3 += v.w;
    }
    float* p = pooled + (size_t)cur_g * WDIM + tid * 4;
    atomicAdd(p + 0, acc0); atomicAdd(p + 1, acc1);
    atomicAdd(p + 2, acc2); atomicAdd(p + 3, acc3);
}

// ---------------------------------------------------------------
extern "C" void kernel_launch(void* const* d_in, const int* in_sizes, int n_in,
                              void* d_out, int out_size)
{
    const float* x      = (const float*)d_in[0];
    const int*   batch  = (const int*)  d_in[1];
    const float* pre_w  = (const float*)d_in[2];
    const float* pre_b  = (const float*)d_in[3];
    const float* mem_w  = (const float*)d_in[4];
    const float* mem_b  = (const float*)d_in[5];
    const float* msg_w  = (const float*)d_in[6];
    const float* msg_b  = (const float*)d_in[7];
    const float* post_w = (const float*)d_in[8];
    const float* post_b = (const float*)d_in[9];
    const float* zero   = (const float*)d_in[10];

    float* out1 = (float*)d_out;
    float* out2 = out1 + (size_t)N_NODES * WDIM;

    float *xraw, *xx, *t, *pooled, *msg;
    cudaGetSymbolAddress((void**)&xraw,   g_xraw);
    cudaGetSymbolAddress((void**)&xx,     g_xx);
    cudaGetSymbolAddress((void**)&t,      g_t);
    cudaGetSymbolAddress((void**)&pooled, g_pooled);
    cudaGetSymbolAddress((void**)&msg,    g_msg);

    const dim3 blk(256);
    const int gy = (N_NODES + BM - 1) / BM;           // 1563

    // 1. zero pooled accumulator
    zero_pooled_kernel<<<(NGRAPH * WDIM + 255) / 256, 256>>>();

    // 2. pre GEMM: xraw = x @ pre_w + pre_b
    gemm_bf16x3<0><<<dim3(WDIM / BN, gy), blk>>>(
        x, pre_w, xraw, N_NODES, WDIM, WDIM, pre_b,
        nullptr, nullptr, nullptr, nullptr);

    // 3. LayerNorm + segment pooling
    ln_pool_kernel<<<N_NODES / LN_ROWS, 128>>>(xraw, xx, pooled, batch);

    // 4. msg GEMM: msg = gelu(pooled @ msg_w + msg_b)
    gemm_bf16x3<1><<<dim3(HDIM / BN, (NGRAPH + BM - 1) / BM), blk>>>(
        pooled, msg_w, msg, NGRAPH, HDIM, WDIM, msg_b,
        nullptr, nullptr, nullptr, nullptr);

    // 5. mem GEMM fused: t = gelu(xx @ mem_w + mem_b) + exp(zero)*msg[batch]
    gemm_bf16x3<2><<<dim3(HDIM / BN, gy), blk>>>(
        xx, mem_w, t, N_NODES, HDIM, WDIM, mem_b,
        msg, batch, zero, nullptr);

    // 6. post GEMM fused: y = t @ post_w + post_b; out1 = x + y; out2 = y
    gemm_bf16x3<3><<<dim3(WDIM / BN, gy), blk>>>(
        t, post_w, out1, N_NODES, WDIM, HDIM, post_b,
        x, nullptr, nullptr, out2);
}

// round 6
// speedup vs baseline: 2.1802x; 1.1803x over previous
#include <cuda_runtime.h>
#include <cuda_bf16.h>
#include <stdint.h>
#include <math.h>

#define N_NODES 200000
#define WDIM    512
#define HDIM    1024
#define NGRAPH  2000

// -------- scratch (__device__ globals) --------
__device__ float g_xraw[(size_t)N_NODES * WDIM];
__device__ float g_pooled[NGRAPH * WDIM];
__device__ float g_msg   [NGRAPH * HDIM];

__device__ __nv_bfloat16 g_xh [(size_t)N_NODES * WDIM];
__device__ __nv_bfloat16 g_xl [(size_t)N_NODES * WDIM];
__device__ __nv_bfloat16 g_xxh[(size_t)N_NODES * WDIM];
__device__ __nv_bfloat16 g_xxl[(size_t)N_NODES * WDIM];
__device__ __nv_bfloat16 g_th [(size_t)N_NODES * HDIM];
__device__ __nv_bfloat16 g_tl [(size_t)N_NODES * HDIM];
__device__ __nv_bfloat16 g_ph [NGRAPH * WDIM];
__device__ __nv_bfloat16 g_pl [NGRAPH * WDIM];

__device__ __nv_bfloat16 g_prewh[WDIM * WDIM],  g_prewl[WDIM * WDIM];
__device__ __nv_bfloat16 g_memwh[WDIM * HDIM],  g_memwl[WDIM * HDIM];
__device__ __nv_bfloat16 g_msgwh[WDIM * HDIM],  g_msgwl[WDIM * HDIM];
__device__ __nv_bfloat16 g_postwh[HDIM * WDIM], g_postwl[HDIM * WDIM];

__global__ void zero_pooled_kernel() {
    int i = blockIdx.x * blockDim.x + threadIdx.x;
    if (i < NGRAPH * WDIM) g_pooled[i] = 0.0f;
}

// split fp32 -> bf16 hi + bf16 lo (grid-stride over float4)
__global__ void split_kernel(const float* __restrict__ src,
                             __nv_bfloat16* __restrict__ h,
                             __nv_bfloat16* __restrict__ l, int n4)
{
    int i = blockIdx.x * blockDim.x + threadIdx.x;
    if (i >= n4) return;
    float4 v = ((const float4*)src)[i];
    __nv_bfloat16 h0 = __float2bfloat16(v.x), h1 = __float2bfloat16(v.y);
    __nv_bfloat16 h2 = __float2bfloat16(v.z), h3 = __float2bfloat16(v.w);
    __nv_bfloat16 l0 = __float2bfloat16(v.x - __bfloat162float(h0));
    __nv_bfloat16 l1 = __float2bfloat16(v.y - __bfloat162float(h1));
    __nv_bfloat16 l2 = __float2bfloat16(v.z - __bfloat162float(h2));
    __nv_bfloat16 l3 = __float2bfloat16(v.w - __bfloat162float(h3));
    ((__nv_bfloat162*)h)[i * 2 + 0] = __halves2bfloat162(h0, h1);
    ((__nv_bfloat162*)h)[i * 2 + 1] = __halves2bfloat162(h2, h3);
    ((__nv_bfloat162*)l)[i * 2 + 0] = __halves2bfloat162(l0, l1);
    ((__nv_bfloat162*)l)[i * 2 + 1] = __halves2bfloat162(l2, l3);
}

// ---------------------------------------------------------------
// split-bf16 tensor-core GEMM, pre-split operands, cp.async 4-stage
// pipeline. 128x128x32 tile, 256 threads (8 warps 2x4), warp 64x32.
// MODE 0: C = acc + bias                               (pre)
// MODE 1: C = gelu(acc + bias)                         (msg)
// MODE 2: th/tl = gelu(acc+bias) + scale*msg[batch[m]] (mem, bf16 split out)
// MODE 3: y = acc + bias; C[m]=x[m]+y; out2[m]=y       (post)
// ---------------------------------------------------------------
#define BM 128
#define BN 128
#define BK 32
#define ASTR 40     // elems: 80B row stride (conflict-free, 16B mult)
#define BSTR 136    // elems: 272B row stride
#define STAGES 4
#define A_H_OFF 0
#define A_L_OFF (BM * ASTR)                 // 5120
#define B_H_OFF (2 * BM * ASTR)             // 10240
#define B_L_OFF (2 * BM * ASTR + BK * BSTR) // 14592
#define STAGE_ELEMS (2 * BM * ASTR + 2 * BK * BSTR)   // 18944
#define SMEM_BYTES (STAGES * STAGE_ELEMS * 2)         // 151552

__device__ __forceinline__ float gelu_exact(float v) {
    return 0.5f * v * (1.0f + erff(v * 0.70710678118654752f));
}
__device__ __forceinline__ unsigned int s2u(const void* p) {
    return (unsigned int)__cvta_generic_to_shared(p);
}
__device__ __forceinline__ void cp16(unsigned int dst, const void* src, int sz) {
    asm volatile("cp.async.cg.shared.global [%0], [%1], 16, %2;"
                 :: "r"(dst), "l"(src), "r"(sz));
}

#define LDSM4(R, ADDR) asm volatile( \
    "ldmatrix.sync.aligned.m8n8.x4.shared.b16 {%0,%1,%2,%3}, [%4];" \
    : "=r"((R)[0]), "=r"((R)[1]), "=r"((R)[2]), "=r"((R)[3]) : "r"(ADDR))

#define LDSM2T(R, ADDR) asm volatile( \
    "ldmatrix.sync.aligned.m8n8.x2.trans.shared.b16 {%0,%1}, [%2];" \
    : "=r"((R)[0]), "=r"((R)[1]) : "r"(ADDR))

#define MMA_BF16(D, Ar, Br) asm volatile( \
    "mma.sync.aligned.m16n8k16.row.col.f32.bf16.bf16.f32 " \
    "{%0,%1,%2,%3},{%4,%5,%6,%7},{%8,%9},{%0,%1,%2,%3};" \
    : "+f"((D)[0]), "+f"((D)[1]), "+f"((D)[2]), "+f"((D)[3]) \
    : "r"((Ar)[0]), "r"((Ar)[1]), "r"((Ar)[2]), "r"((Ar)[3]), \
      "r"((Br)[0]), "r"((Br)[1]))

template<int MODE>
__global__ __launch_bounds__(256, 1)
void gemm_split(const __nv_bfloat16* __restrict__ Agh, const __nv_bfloat16* __restrict__ Agl,
                const __nv_bfloat16* __restrict__ Bgh, const __nv_bfloat16* __restrict__ Bgl,
                float* __restrict__ C, int M, int N, int K,
                const float* __restrict__ bias,
                const float* __restrict__ extra,   // MODE2: g_msg, MODE3: x
                const int*   __restrict__ batch,
                const float* __restrict__ zero,
                __nv_bfloat16* __restrict__ outh,
                __nv_bfloat16* __restrict__ outl,
                float* __restrict__ out2)
{
    extern __shared__ __nv_bfloat16 smem[];

    const int tid  = threadIdx.x;
    const int lane = tid & 31, warp = tid >> 5;
    const int warp_m = warp >> 2;
    const int warp_n = warp & 3;
    const int bm = blockIdx.y * BM;
    const int bn = blockIdx.x * BN;

    float acc[4][4][4];
    #pragma unroll
    for (int a = 0; a < 4; a++)
        #pragma unroll
        for (int b = 0; b < 4; b++)
            #pragma unroll
            for (int c = 0; c < 4; c++) acc[a][b][c] = 0.0f;

    const int KT = K / BK;

    auto issue = [&](int s, int k0) {
        __nv_bfloat16* base = smem + s * STAGE_ELEMS;
        #pragma unroll
        for (int i = 0; i < 2; i++) {
            int c = tid + 256 * i;
            int row = c >> 2, coff = (c & 3) * 8;
            int gm = bm + row;
            int p = (gm < M) ? 16 : 0;
            size_t go = (size_t)(p ? gm : 0) * K + k0 + coff;
            cp16(s2u(base + A_H_OFF + row * ASTR + coff), Agh + go, p);
            cp16(s2u(base + A_L_OFF + row * ASTR + coff), Agl + go, p);
        }
        #pragma unroll
        for (int i = 0; i < 2; i++) {
            int c = tid + 256 * i;
            int row = c >> 4, coff = (c & 15) * 8;
            size_t go = (size_t)(k0 + row) * N + bn + coff;
            cp16(s2u(base + B_H_OFF + row * BSTR + coff), Bgh + go, 16);
            cp16(s2u(base + B_L_OFF + row * BSTR + coff), Bgl + go, 16);
        }
    };

    auto compute = [&](int s) {
        __nv_bfloat16* base = smem + s * STAGE_ELEMS;
        #pragma unroll
        for (int kk = 0; kk < 2; kk++) {
            unsigned int ah[4][4], al[4][4], bh[4][2], bl[4][2];
            #pragma unroll
            for (int mt = 0; mt < 4; mt++) {
                int row = warp_m * 64 + mt * 16 + (lane & 15);
                int col = kk * 16 + (lane >> 4) * 8;
                LDSM4(ah[mt], s2u(base + A_H_OFF + row * ASTR + col));
                LDSM4(al[mt], s2u(base + A_L_OFF + row * ASTR + col));
            }
            #pragma unroll
            for (int nt = 0; nt < 4; nt++) {
                int row = kk * 16 + (lane & 15);
                int col = warp_n * 32 + nt * 8;
                LDSM2T(bh[nt], s2u(base + B_H_OFF + row * BSTR + col));
                LDSM2T(bl[nt], s2u(base + B_L_OFF + row * BSTR + col));
            }
            #pragma unroll
            for (int mt = 0; mt < 4; mt++)
                #pragma unroll
                for (int nt = 0; nt < 4; nt++) {
                    MMA_BF16(acc[mt][nt], ah[mt], bh[nt]);
                    MMA_BF16(acc[mt][nt], ah[mt], bl[nt]);
                    MMA_BF16(acc[mt][nt], al[mt], bh[nt]);
                }
        }
    };

    // prologue: prefetch STAGES-1 stages
    #pragma unroll
    for (int s = 0; s < STAGES - 1; s++) {
        if (s < KT) issue(s, s * BK);
        asm volatile("cp.async.commit_group;");
    }

    for (int kt = 0; kt < KT; kt++) {
        asm volatile("cp.async.wait_group %0;" :: "n"(STAGES - 2));
        __syncthreads();
        compute(kt % STAGES);
        int next = kt + STAGES - 1;
        if (next < KT) issue(next % STAGES, next * BK);
        asm volatile("cp.async.commit_group;");
    }

    // ---------------- epilogue ----------------
    float scale = 1.0f;
    if (MODE == 2) scale = expf(zero[0]);

    #pragma unroll
    for (int mt = 0; mt < 4; mt++) {
        const int rbase = bm + warp_m * 64 + mt * 16 + (lane >> 2);
        #pragma unroll
        for (int half = 0; half < 2; half++) {
            const int row = rbase + half * 8;
            if (row >= M) continue;
            int g = 0;
            if (MODE == 2) g = batch[row];
            #pragma unroll
            for (int nt = 0; nt < 4; nt++) {
                const int col = bn + warp_n * 32 + nt * 8 + (lane & 3) * 2;
                float v0 = acc[mt][nt][half * 2 + 0] + bias[col];
                float v1 = acc[mt][nt][half * 2 + 1] + bias[col + 1];
                if (MODE == 1 || MODE == 2) {
                    v0 = gelu_exact(v0);
                    v1 = gelu_exact(v1);
                }
                if (MODE == 2) {
                    float2 mv = *(const float2*)(extra + (size_t)g * N + col);
                    v0 += scale * mv.x;
                    v1 += scale * mv.y;
                    __nv_bfloat16 h0 = __float2bfloat16(v0);
                    __nv_bfloat16 h1 = __float2bfloat16(v1);
                    __nv_bfloat16 l0 = __float2bfloat16(v0 - __bfloat162float(h0));
                    __nv_bfloat16 l1 = __float2bfloat16(v1 - __bfloat162float(h1));
                    *(__nv_bfloat162*)(outh + (size_t)row * N + col) = __halves2bfloat162(h0, h1);
                    *(__nv_bfloat162*)(outl + (size_t)row * N + col) = __halves2bfloat162(l0, l1);
                } else if (MODE == 3) {
                    float2 xv = *(const float2*)(extra + (size_t)row * N + col);
                    *(float2*)(out2 + (size_t)row * N + col) = make_float2(v0, v1);
                    *(float2*)(C + (size_t)row * N + col) =
                        make_float2(xv.x + v0, xv.y + v1);
                } else {
                    *(float2*)(C + (size_t)row * N + col) = make_float2(v0, v1);
                }
            }
        }
    }
}

// ---------------------------------------------------------------
// LayerNorm + segment pooling; writes xx as bf16 hi/lo split.
// ---------------------------------------------------------------
#define LN_ROWS 32
__global__ __launch_bounds__(128)
void ln_pool_kernel(const float* __restrict__ xraw,
                    __nv_bfloat16* __restrict__ xxh,
                    __nv_bfloat16* __restrict__ xxl,
                    float* __restrict__ pooled, const int* __restrict__ batch)
{
    __shared__ float shs[4], shs2[4];
    const int tid  = threadIdx.x;
    const int lane = tid & 31, warp = tid >> 5;
    const int row0 = blockIdx.x * LN_ROWS;

    float acc0 = 0.f, acc1 = 0.f, acc2 = 0.f, acc3 = 0.f;
    int cur_g = batch[row0];

    for (int r = 0; r < LN_ROWS; r++) {
        const int row = row0 + r;
        float4 v = *(const float4*)(xraw + (size_t)row * WDIM + tid * 4);
        float s  = v.x + v.y + v.z + v.w;
        float s2 = v.x * v.x + v.y * v.y + v.z * v.z + v.w * v.w;
        #pragma unroll
        for (int o = 16; o > 0; o >>= 1) {
            s  += __shfl_xor_sync(0xffffffffu, s,  o);
            s2 += __shfl_xor_sync(0xffffffffu, s2, o);
        }
        if (lane == 0) { shs[warp] = s; shs2[warp] = s2; }
        __syncthreads();
        float sum  = shs[0] + shs[1] + shs[2] + shs[3];
        float sum2 = shs2[0] + shs2[1] + shs2[2] + shs2[3];
        __syncthreads();

        const float mu  = sum * (1.0f / WDIM);
        const float var = sum2 * (1.0f / WDIM) - mu * mu;
        const float rs  = rsqrtf(var + 1e-5f);
        v.x = (v.x - mu) * rs; v.y = (v.y - mu) * rs;
        v.z = (v.z - mu) * rs; v.w = (v.w - mu) * rs;

        __nv_bfloat16 h0 = __float2bfloat16(v.x), h1 = __float2bfloat16(v.y);
        __nv_bfloat16 h2 = __float2bfloat16(v.z), h3 = __float2bfloat16(v.w);
        __nv_bfloat16 l0 = __float2bfloat16(v.x - __bfloat162float(h0));
        __nv_bfloat16 l1 = __float2bfloat16(v.y - __bfloat162float(h1));
        __nv_bfloat16 l2 = __float2bfloat16(v.z - __bfloat162float(h2));
        __nv_bfloat16 l3 = __float2bfloat16(v.w - __bfloat162float(h3));
        size_t o = (size_t)row * WDIM + tid * 4;
        *(__nv_bfloat162*)(xxh + o + 0) = __halves2bfloat162(h0, h1);
        *(__nv_bfloat162*)(xxh + o + 2) = __halves2bfloat162(h2, h3);
        *(__nv_bfloat162*)(xxl + o + 0) = __halves2bfloat162(l0, l1);
        *(__nv_bfloat162*)(xxl + o + 2) = __halves2bfloat162(l2, l3);

        const int g = batch[row];
        if (g != cur_g) {
            float* p = pooled + (size_t)cur_g * WDIM + tid * 4;
            atomicAdd(p + 0, acc0); atomicAdd(p + 1, acc1);
            atomicAdd(p + 2, acc2); atomicAdd(p + 3, acc3);
            acc0 = acc1 = acc2 = acc3 = 0.f;
            cur_g = g;
        }
        acc0 += v.x; acc1 += v.y; acc2 += v.z; acc3 += v.w;
    }
    float* p = pooled + (size_t)cur_g * WDIM + tid * 4;
    atomicAdd(p + 0, acc0); atomicAdd(p + 1, acc1);
    atomicAdd(p + 2, acc2); atomicAdd(p + 3, acc3);
}

// ---------------------------------------------------------------
extern "C" void kernel_launch(void* const* d_in, const int* in_sizes, int n_in,
                              void* d_out, int out_size)
{
    const float* x      = (const float*)d_in[0];
    const int*   batch  = (const int*)  d_in[1];
    const float* pre_w  = (const float*)d_in[2];
    const float* pre_b  = (const float*)d_in[3];
    const float* mem_w  = (const float*)d_in[4];
    const float* mem_b  = (const float*)d_in[5];
    const float* msg_w  = (const float*)d_in[6];
    const float* msg_b  = (const float*)d_in[7];
    const float* post_w = (const float*)d_in[8];
    const float* post_b = (const float*)d_in[9];
    const float* zero   = (const float*)d_in[10];

    float* out1 = (float*)d_out;
    float* out2 = out1 + (size_t)N_NODES * WDIM;

    float *xraw, *pooled, *msg;
    __nv_bfloat16 *xh, *xl, *xxh, *xxl, *th, *tl, *ph, *pl;
    __nv_bfloat16 *prewh, *prewl, *memwh, *memwl, *msgwh, *msgwl, *postwh, *postwl;
    cudaGetSymbolAddress((void**)&xraw,   g_xraw);
    cudaGetSymbolAddress((void**)&pooled, g_pooled);
    cudaGetSymbolAddress((void**)&msg,    g_msg);
    cudaGetSymbolAddress((void**)&xh,  g_xh);   cudaGetSymbolAddress((void**)&xl,  g_xl);
    cudaGetSymbolAddress((void**)&xxh, g_xxh);  cudaGetSymbolAddress((void**)&xxl, g_xxl);
    cudaGetSymbolAddress((void**)&th,  g_th);   cudaGetSymbolAddress((void**)&tl,  g_tl);
    cudaGetSymbolAddress((void**)&ph,  g_ph);   cudaGetSymbolAddress((void**)&pl,  g_pl);
    cudaGetSymbolAddress((void**)&prewh,  g_prewh);  cudaGetSymbolAddress((void**)&prewl,  g_prewl);
    cudaGetSymbolAddress((void**)&memwh,  g_memwh);  cudaGetSymbolAddress((void**)&memwl,  g_memwl);
    cudaGetSymbolAddress((void**)&msgwh,  g_msgwh);  cudaGetSymbolAddress((void**)&msgwl,  g_msgwl);
    cudaGetSymbolAddress((void**)&postwh, g_postwh); cudaGetSymbolAddress((void**)&postwl, g_postwl);

    cudaFuncSetAttribute(gemm_split<0>, cudaFuncAttributeMaxDynamicSharedMemorySize, SMEM_BYTES);
    cudaFuncSetAttribute(gemm_split<1>, cudaFuncAttributeMaxDynamicSharedMemorySize, SMEM_BYTES);
    cudaFuncSetAttribute(gemm_split<2>, cudaFuncAttributeMaxDynamicSharedMemorySize, SMEM_BYTES);
    cudaFuncSetAttribute(gemm_split<3>, cudaFuncAttributeMaxDynamicSharedMemorySize, SMEM_BYTES);

    const dim3 blk(256);
    const int gy = (N_NODES + BM - 1) / BM;           // 1563

    // 0. splits + zero
    zero_pooled_kernel<<<(NGRAPH * WDIM + 255) / 256, 256>>>();
    {
        int n4 = (int)((size_t)N_NODES * WDIM / 4);
        split_kernel<<<(n4 + 255) / 256, 256>>>(x, xh, xl, n4);
        split_kernel<<<(WDIM * WDIM / 4 + 255) / 256, 256>>>(pre_w,  prewh,  prewl,  WDIM * WDIM / 4);
        split_kernel<<<(WDIM * HDIM / 4 + 255) / 256, 256>>>(mem_w,  memwh,  memwl,  WDIM * HDIM / 4);
        split_kernel<<<(WDIM * HDIM / 4 + 255) / 256, 256>>>(msg_w,  msgwh,  msgwl,  WDIM * HDIM / 4);
        split_kernel<<<(HDIM * WDIM / 4 + 255) / 256, 256>>>(post_w, postwh, postwl, HDIM * WDIM / 4);
    }

    // 1. pre GEMM: xraw = x @ pre_w + pre_b
    gemm_split<0><<<dim3(WDIM / BN, gy), blk, SMEM_BYTES>>>(
        xh, xl, prewh, prewl, xraw, N_NODES, WDIM, WDIM, pre_b,
        nullptr, nullptr, nullptr, nullptr, nullptr, nullptr);

    // 2. LayerNorm + segment pooling (-> xxh/xxl split, pooled fp32)
    ln_pool_kernel<<<N_NODES / LN_ROWS, 128>>>(xraw, xxh, xxl, pooled, batch);

    // 3. split pooled
    split_kernel<<<(NGRAPH * WDIM / 4 + 255) / 256, 256>>>(pooled, ph, pl, NGRAPH * WDIM / 4);

    // 4. msg GEMM: msg = gelu(pooled @ msg_w + msg_b)
    gemm_split<1><<<dim3(HDIM / BN, (NGRAPH + BM - 1) / BM), blk, SMEM_BYTES>>>(
        ph, pl, msgwh, msgwl, msg, NGRAPH, HDIM, WDIM, msg_b,
        nullptr, nullptr, nullptr, nullptr, nullptr, nullptr);

    // 5. mem GEMM fused: t(h/l) = gelu(xx @ mem_w + mem_b) + exp(zero)*msg[batch]
    gemm_split<2><<<dim3(HDIM / BN, gy), blk, SMEM_BYTES>>>(
        xxh, xxl, memwh, memwl, nullptr, N_NODES, HDIM, WDIM, mem_b,
        msg, batch, zero, th, tl, nullptr);

    // 6. post GEMM fused: y = t @ post_w + post_b; out1 = x + y; out2 = y
    gemm_split<3><<<dim3(WDIM / BN, gy), blk, SMEM_BYTES>>>(
        th, tl, postwh, postwl, out1, N_NODES, WDIM, HDIM, post_b,
        x, nullptr, nullptr, nullptr, nullptr, out2);
}

// round 7
// speedup vs baseline: 3.3329x; 1.5287x over previous
#include <cuda_runtime.h>
#include <cuda_fp16.h>
#include <stdint.h>
#include <math.h>

#define N_NODES 200000
#define WDIM    512
#define HDIM    1024
#define NGRAPH  2000

// -------- scratch (__device__ globals) --------
__device__ float g_xraw[(size_t)N_NODES * WDIM];
__device__ float g_pooled[NGRAPH * WDIM];
__device__ float g_msg   [NGRAPH * HDIM];

__device__ __half g_xh [(size_t)N_NODES * WDIM];
__device__ __half g_xl [(size_t)N_NODES * WDIM];
__device__ __half g_xxh[(size_t)N_NODES * WDIM];
__device__ __half g_xxl[(size_t)N_NODES * WDIM];
__device__ __half g_th [(size_t)N_NODES * HDIM];
__device__ __half g_tl [(size_t)N_NODES * HDIM];
__device__ __half g_ph [NGRAPH * WDIM];
__device__ __half g_pl [NGRAPH * WDIM];

__device__ __half g_prew [WDIM * WDIM];
__device__ __half g_memw [WDIM * HDIM];
__device__ __half g_msgw [WDIM * HDIM];
__device__ __half g_postw[HDIM * WDIM];

__global__ void zero_pooled_kernel() {
    int i = blockIdx.x * blockDim.x + threadIdx.x;
    if (i < NGRAPH * WDIM) g_pooled[i] = 0.0f;
}

// split fp32 -> fp16 hi + fp16 lo
__global__ void split_kernel(const float* __restrict__ src,
                             __half* __restrict__ h,
                             __half* __restrict__ l, int n4)
{
    int i = blockIdx.x * blockDim.x + threadIdx.x;
    if (i >= n4) return;
    float4 v = ((const float4*)src)[i];
    __half h0 = __float2half_rn(v.x), h1 = __float2half_rn(v.y);
    __half h2 = __float2half_rn(v.z), h3 = __float2half_rn(v.w);
    __half l0 = __float2half_rn(v.x - __half2float(h0));
    __half l1 = __float2half_rn(v.y - __half2float(h1));
    __half l2 = __float2half_rn(v.z - __half2float(h2));
    __half l3 = __float2half_rn(v.w - __half2float(h3));
    ((__half2*)h)[i * 2 + 0] = __halves2half2(h0, h1);
    ((__half2*)h)[i * 2 + 1] = __halves2half2(h2, h3);
    ((__half2*)l)[i * 2 + 0] = __halves2half2(l0, l1);
    ((__half2*)l)[i * 2 + 1] = __halves2half2(l2, l3);
}

// convert fp32 -> single fp16 (weights)
__global__ void conv_kernel(const float* __restrict__ src,
                            __half* __restrict__ h, int n4)
{
    int i = blockIdx.x * blockDim.x + threadIdx.x;
    if (i >= n4) return;
    float4 v = ((const float4*)src)[i];
    ((__half2*)h)[i * 2 + 0] = __halves2half2(__float2half_rn(v.x), __float2half_rn(v.y));
    ((__half2*)h)[i * 2 + 1] = __halves2half2(__float2half_rn(v.z), __float2half_rn(v.w));
}

// ---------------------------------------------------------------
// fp16 2-product tensor-core GEMM: C = Ahi@B + Alo@B  (B single fp16)
// 128x128x32 tile, 256 threads (8 warps 2x4), warp 64x32,
// cp.async 3-stage pipeline, 2 CTAs/SM.
// MODE 0: C = acc + bias                               (pre)
// MODE 1: C = gelu(acc + bias)                         (msg)
// MODE 2: th/tl = gelu(acc+bias) + scale*msg[batch[m]] (mem, fp16 split out)
// MODE 3: y = acc + bias; C[m]=x[m]+y; out2[m]=y       (post)
// ---------------------------------------------------------------
#define BM 128
#define BN 128
#define BK 32
#define ASTR 40     // elems: 80B row stride
#define BSTR 136    // elems: 272B row stride
#define STAGES 3
#define A_H_OFF 0
#define A_L_OFF (BM * ASTR)                 // 5120
#define B_OFF   (2 * BM * ASTR)             // 10240
#define STAGE_ELEMS (2 * BM * ASTR + BK * BSTR)   // 14592
#define SMEM_BYTES (STAGES * STAGE_ELEMS * 2)     // 87552

__device__ __forceinline__ float gelu_exact(float v) {
    return 0.5f * v * (1.0f + erff(v * 0.70710678118654752f));
}
__device__ __forceinline__ unsigned int s2u(const void* p) {
    return (unsigned int)__cvta_generic_to_shared(p);
}
__device__ __forceinline__ void cp16(unsigned int dst, const void* src, int sz) {
    asm volatile("cp.async.cg.shared.global [%0], [%1], 16, %2;"
                 :: "r"(dst), "l"(src), "r"(sz));
}

#define LDSM4(R, ADDR) asm volatile( \
    "ldmatrix.sync.aligned.m8n8.x4.shared.b16 {%0,%1,%2,%3}, [%4];" \
    : "=r"((R)[0]), "=r"((R)[1]), "=r"((R)[2]), "=r"((R)[3]) : "r"(ADDR))

#define LDSM2T(R, ADDR) asm volatile( \
    "ldmatrix.sync.aligned.m8n8.x2.trans.shared.b16 {%0,%1}, [%2];" \
    : "=r"((R)[0]), "=r"((R)[1]) : "r"(ADDR))

#define MMA_F16(D, Ar, Br) asm volatile( \
    "mma.sync.aligned.m16n8k16.row.col.f32.f16.f16.f32 " \
    "{%0,%1,%2,%3},{%4,%5,%6,%7},{%8,%9},{%0,%1,%2,%3};" \
    : "+f"((D)[0]), "+f"((D)[1]), "+f"((D)[2]), "+f"((D)[3]) \
    : "r"((Ar)[0]), "r"((Ar)[1]), "r"((Ar)[2]), "r"((Ar)[3]), \
      "r"((Br)[0]), "r"((Br)[1]))

template<int MODE>
__global__ __launch_bounds__(256, 2)
void gemm_split(const __half* __restrict__ Agh, const __half* __restrict__ Agl,
                const __half* __restrict__ Bg,
                float* __restrict__ C, int M, int N, int K,
                const float* __restrict__ bias,
                const float* __restrict__ extra,   // MODE2: g_msg, MODE3: x
                const int*   __restrict__ batch,
                const float* __restrict__ zero,
                __half* __restrict__ outh,
                __half* __restrict__ outl,
                float* __restrict__ out2)
{
    extern __shared__ __half smem[];

    const int tid  = threadIdx.x;
    const int lane = tid & 31, warp = tid >> 5;
    const int warp_m = warp >> 2;
    const int warp_n = warp & 3;
    const int bm = blockIdx.y * BM;
    const int bn = blockIdx.x * BN;

    float acc[4][4][4];
    #pragma unroll
    for (int a = 0; a < 4; a++)
        #pragma unroll
        for (int b = 0; b < 4; b++)
            #pragma unroll
            for (int c = 0; c < 4; c++) acc[a][b][c] = 0.0f;

    const int KT = K / BK;

    auto issue = [&](int s, int k0) {
        __half* base = smem + s * STAGE_ELEMS;
        #pragma unroll
        for (int i = 0; i < 2; i++) {
            int c = tid + 256 * i;
            int row = c >> 2, coff = (c & 3) * 8;
            int gm = bm + row;
            int p = (gm < M) ? 16 : 0;
            size_t go = (size_t)(p ? gm : 0) * K + k0 + coff;
            cp16(s2u(base + A_H_OFF + row * ASTR + coff), Agh + go, p);
            cp16(s2u(base + A_L_OFF + row * ASTR + coff), Agl + go, p);
        }
        #pragma unroll
        for (int i = 0; i < 2; i++) {
            int c = tid + 256 * i;
            int row = c >> 4, coff = (c & 15) * 8;
            size_t go = (size_t)(k0 + row) * N + bn + coff;
            cp16(s2u(base + B_OFF + row * BSTR + coff), Bg + go, 16);
        }
    };

    auto compute = [&](int s) {
        __half* base = smem + s * STAGE_ELEMS;
        #pragma unroll
        for (int kk = 0; kk < 2; kk++) {
            unsigned int ah[4][4], al[4][4], bb[4][2];
            #pragma unroll
            for (int mt = 0; mt < 4; mt++) {
                int row = warp_m * 64 + mt * 16 + (lane & 15);
                int col = kk * 16 + (lane >> 4) * 8;
                LDSM4(ah[mt], s2u(base + A_H_OFF + row * ASTR + col));
                LDSM4(al[mt], s2u(base + A_L_OFF + row * ASTR + col));
            }
            #pragma unroll
            for (int nt = 0; nt < 4; nt++) {
                int row = kk * 16 + (lane & 15);
                int col = warp_n * 32 + nt * 8;
                LDSM2T(bb[nt], s2u(base + B_OFF + row * BSTR + col));
            }
            #pragma unroll
            for (int mt = 0; mt < 4; mt++)
                #pragma unroll
                for (int nt = 0; nt < 4; nt++) {
                    MMA_F16(acc[mt][nt], ah[mt], bb[nt]);
                    MMA_F16(acc[mt][nt], al[mt], bb[nt]);
                }
        }
    };

    // prologue: prefetch STAGES-1 stages
    #pragma unroll
    for (int s = 0; s < STAGES - 1; s++) {
        if (s < KT) issue(s, s * BK);
        asm volatile("cp.async.commit_group;");
    }

    for (int kt = 0; kt < KT; kt++) {
        asm volatile("cp.async.wait_group %0;" :: "n"(STAGES - 2));
        __syncthreads();
        compute(kt % STAGES);
        int next = kt + STAGES - 1;
        if (next < KT) issue(next % STAGES, next * BK);
        asm volatile("cp.async.commit_group;");
    }

    // ---------------- epilogue ----------------
    float scale = 1.0f;
    if (MODE == 2) scale = expf(zero[0]);

    #pragma unroll
    for (int mt = 0; mt < 4; mt++) {
        const int rbase = bm + warp_m * 64 + mt * 16 + (lane >> 2);
        #pragma unroll
        for (int half = 0; half < 2; half++) {
            const int row = rbase + half * 8;
            if (row >= M) continue;
            int g = 0;
            if (MODE == 2) g = batch[row];
            #pragma unroll
            for (int nt = 0; nt < 4; nt++) {
                const int col = bn + warp_n * 32 + nt * 8 + (lane & 3) * 2;
                float v0 = acc[mt][nt][half * 2 + 0] + bias[col];
                float v1 = acc[mt][nt][half * 2 + 1] + bias[col + 1];
                if (MODE == 1 || MODE == 2) {
                    v0 = gelu_exact(v0);
                    v1 = gelu_exact(v1);
                }
                if (MODE == 2) {
                    float2 mv = *(const float2*)(extra + (size_t)g * N + col);
                    v0 += scale * mv.x;
                    v1 += scale * mv.y;
                    __half h0 = __float2half_rn(v0);
                    __half h1 = __float2half_rn(v1);
                    __half l0 = __float2half_rn(v0 - __half2float(h0));
                    __half l1 = __float2half_rn(v1 - __half2float(h1));
                    *(__half2*)(outh + (size_t)row * N + col) = __halves2half2(h0, h1);
                    *(__half2*)(outl + (size_t)row * N + col) = __halves2half2(l0, l1);
                } else if (MODE == 3) {
                    float2 xv = *(const float2*)(extra + (size_t)row * N + col);
                    *(float2*)(out2 + (size_t)row * N + col) = make_float2(v0, v1);
                    *(float2*)(C + (size_t)row * N + col) =
                        make_float2(xv.x + v0, xv.y + v1);
                } else {
                    *(float2*)(C + (size_t)row * N + col) = make_float2(v0, v1);
                }
            }
        }
    }
}

// ---------------------------------------------------------------
// LayerNorm + segment pooling; writes xx as fp16 hi/lo split.
// ---------------------------------------------------------------
#define LN_ROWS 32
__global__ __launch_bounds__(128)
void ln_pool_kernel(const float* __restrict__ xraw,
                    __half* __restrict__ xxh,
                    __half* __restrict__ xxl,
                    float* __restrict__ pooled, const int* __restrict__ batch)
{
    __shared__ float shs[4], shs2[4];
    const int tid  = threadIdx.x;
    const int lane = tid & 31, warp = tid >> 5;
    const int row0 = blockIdx.x * LN_ROWS;

    float acc0 = 0.f, acc1 = 0.f, acc2 = 0.f, acc3 = 0.f;
    int cur_g = batch[row0];

    for (int r = 0; r < LN_ROWS; r++) {
        const int row = row0 + r;
        float4 v = *(const float4*)(xraw + (size_t)row * WDIM + tid * 4);
        float s  = v.x + v.y + v.z + v.w;
        float s2 = v.x * v.x + v.y * v.y + v.z * v.z + v.w * v.w;
        #pragma unroll
        for (int o = 16; o > 0; o >>= 1) {
            s  += __shfl_xor_sync(0xffffffffu, s,  o);
            s2 += __shfl_xor_sync(0xffffffffu, s2, o);
        }
        if (lane == 0) { shs[warp] = s; shs2[warp] = s2; }
        __syncthreads();
        float sum  = shs[0] + shs[1] + shs[2] + shs[3];
        float sum2 = shs2[0] + shs2[1] + shs2[2] + shs2[3];
        __syncthreads();

        const float mu  = sum * (1.0f / WDIM);
        const float var = sum2 * (1.0f / WDIM) - mu * mu;
        const float rs  = rsqrtf(var + 1e-5f);
        v.x = (v.x - mu) * rs; v.y = (v.y - mu) * rs;
        v.z = (v.z - mu) * rs; v.w = (v.w - mu) * rs;

        __half h0 = __float2half_rn(v.x), h1 = __float2half_rn(v.y);
        __half h2 = __float2half_rn(v.z), h3 = __float2half_rn(v.w);
        __half l0 = __float2half_rn(v.x - __half2float(h0));
        __half l1 = __float2half_rn(v.y - __half2float(h1));
        __half l2 = __float2half_rn(v.z - __half2float(h2));
        __half l3 = __float2half_rn(v.w - __half2float(h3));
        size_t o = (size_t)row * WDIM + tid * 4;
        *(__half2*)(xxh + o + 0) = __halves2half2(h0, h1);
        *(__half2*)(xxh + o + 2) = __halves2half2(h2, h3);
        *(__half2*)(xxl + o + 0) = __halves2half2(l0, l1);
        *(__half2*)(xxl + o + 2) = __halves2half2(l2, l3);

        const int g = batch[row];
        if (g != cur_g) {
            float* p = pooled + (size_t)cur_g * WDIM + tid * 4;
            atomicAdd(p + 0, acc0); atomicAdd(p + 1, acc1);
            atomicAdd(p + 2, acc2); atomicAdd(p + 3, acc3);
            acc0 = acc1 = acc2 = acc3 = 0.f;
            cur_g = g;
        }
        acc0 += v.x; acc1 += v.y; acc2 += v.z; acc3 += v.w;
    }
    float* p = pooled + (size_t)cur_g * WDIM + tid * 4;
    atomicAdd(p + 0, acc0); atomicAdd(p + 1, acc1);
    atomicAdd(p + 2, acc2); atomicAdd(p + 3, acc3);
}

// ---------------------------------------------------------------
extern "C" void kernel_launch(void* const* d_in, const int* in_sizes, int n_in,
                              void* d_out, int out_size)
{
    const float* x      = (const float*)d_in[0];
    const int*   batch  = (const int*)  d_in[1];
    const float* pre_w  = (const float*)d_in[2];
    const float* pre_b  = (const float*)d_in[3];
    const float* mem_w  = (const float*)d_in[4];
    const float* mem_b  = (const float*)d_in[5];
    const float* msg_w  = (const float*)d_in[6];
    const float* msg_b  = (const float*)d_in[7];
    const float* post_w = (const float*)d_in[8];
    const float* post_b = (const float*)d_in[9];
    const float* zero   = (const float*)d_in[10];

    float* out1 = (float*)d_out;
    float* out2 = out1 + (size_t)N_NODES * WDIM;

    float *xraw, *pooled, *msg;
    __half *xh, *xl, *xxh, *xxl, *th, *tl, *ph, *pl;
    __half *prew, *memw, *msgw, *postw;
    cudaGetSymbolAddress((void**)&xraw,   g_xraw);
    cudaGetSymbolAddress((void**)&pooled, g_pooled);
    cudaGetSymbolAddress((void**)&msg,    g_msg);
    cudaGetSymbolAddress((void**)&xh,  g_xh);   cudaGetSymbolAddress((void**)&xl,  g_xl);
    cudaGetSymbolAddress((void**)&xxh, g_xxh);  cudaGetSymbolAddress((void**)&xxl, g_xxl);
    cudaGetSymbolAddress((void**)&th,  g_th);   cudaGetSymbolAddress((void**)&tl,  g_tl);
    cudaGetSymbolAddress((void**)&ph,  g_ph);   cudaGetSymbolAddress((void**)&pl,  g_pl);
    cudaGetSymbolAddress((void**)&prew,  g_prew);
    cudaGetSymbolAddress((void**)&memw,  g_memw);
    cudaGetSymbolAddress((void**)&msgw,  g_msgw);
    cudaGetSymbolAddress((void**)&postw, g_postw);

    cudaFuncSetAttribute(gemm_split<0>, cudaFuncAttributeMaxDynamicSharedMemorySize, SMEM_BYTES);
    cudaFuncSetAttribute(gemm_split<1>, cudaFuncAttributeMaxDynamicSharedMemorySize, SMEM_BYTES);
    cudaFuncSetAttribute(gemm_split<2>, cudaFuncAttributeMaxDynamicSharedMemorySize, SMEM_BYTES);
    cudaFuncSetAttribute(gemm_split<3>, cudaFuncAttributeMaxDynamicSharedMemorySize, SMEM_BYTES);

    const dim3 blk(256);
    const int gy = (N_NODES + BM - 1) / BM;           // 1563

    // 0. splits + conversions + zero
    zero_pooled_kernel<<<(NGRAPH * WDIM + 255) / 256, 256>>>();
    {
        int n4 = (int)((size_t)N_NODES * WDIM / 4);
        split_kernel<<<(n4 + 255) / 256, 256>>>(x, xh, xl, n4);
        conv_kernel<<<(WDIM * WDIM / 4 + 255) / 256, 256>>>(pre_w,  prew,  WDIM * WDIM / 4);
        conv_kernel<<<(WDIM * HDIM / 4 + 255) / 256, 256>>>(mem_w,  memw,  WDIM * HDIM / 4);
        conv_kernel<<<(WDIM * HDIM / 4 + 255) / 256, 256>>>(msg_w,  msgw,  WDIM * HDIM / 4);
        conv_kernel<<<(HDIM * WDIM / 4 + 255) / 256, 256>>>(post_w, postw, HDIM * WDIM / 4);
    }

    // 1. pre GEMM: xraw = x @ pre_w + pre_b
    gemm_split<0><<<dim3(WDIM / BN, gy), blk, SMEM_BYTES>>>(
        xh, xl, prew, xraw, N_NODES, WDIM, WDIM, pre_b,
        nullptr, nullptr, nullptr, nullptr, nullptr, nullptr);

    // 2. LayerNorm + segment pooling (-> xxh/xxl split, pooled fp32)
    ln_pool_kernel<<<N_NODES / LN_ROWS, 128>>>(xraw, xxh, xxl, pooled, batch);

    // 3. split pooled
    split_kernel<<<(NGRAPH * WDIM / 4 + 255) / 256, 256>>>(pooled, ph, pl, NGRAPH * WDIM / 4);

    // 4. msg GEMM: msg = gelu(pooled @ msg_w + msg_b)
    gemm_split<1><<<dim3(HDIM / BN, (NGRAPH + BM - 1) / BM), blk, SMEM_BYTES>>>(
        ph, pl, msgw, msg, NGRAPH, HDIM, WDIM, msg_b,
        nullptr, nullptr, nullptr, nullptr, nullptr, nullptr);

    // 5. mem GEMM fused: t(h/l) = gelu(xx @ mem_w + mem_b) + exp(zero)*msg[batch]
    gemm_split<2><<<dim3(HDIM / BN, gy), blk, SMEM_BYTES>>>(
        xxh, xxl, memw, nullptr, N_NODES, HDIM, WDIM, mem_b,
        msg, batch, zero, th, tl, nullptr);

    // 6. post GEMM fused: y = t @ post_w + post_b; out1 = x + y; out2 = y
    gemm_split<3><<<dim3(WDIM / BN, gy), blk, SMEM_BYTES>>>(
        th, tl, postw, out1, N_NODES, WDIM, HDIM, post_b,
        x, nullptr, nullptr, nullptr, nullptr, out2);
}